// round 4
// baseline (speedup 1.0000x reference)
#include <cuda_runtime.h>
#include <cstdint>

// ============================================================================
// ShiftConv as gather-GEMM, tf32 mma.sync (sm_80+ PTX, runs on plain sm_103):
//   out[n,d,y,x] = sum_c x[n,c,y+sh[c],x+sw[c]] * W[c,d] + bias[d]
// M = 131072 pixels, K = 256, N = 256.
// CTA tile 64(M) x 256(N), 256 threads (8 warps, warp tile 64x32),
// 2 CTAs/SM for phase-interleaved latency hiding. K chunked 8 x 32,
// double-buffered, float2-packed mma fragments in smem.
// ============================================================================

#define CIN   256
#define NOUT  256
#define HW    4096

// A stage: float2[4 ks][64 m][4 a]  (8 KB), swizzle a ^= (m>>2)&3
#define A_F2   1024
// B stage: float2[4 ks][256 n][4 a] (32 KB), swizzle a ^= n&2 (baked in gmem)
#define B_F2   4096

__device__ float2 g_wp[CIN * NOUT / 2];   // packed tf32 weight (512 KB)

static __device__ __forceinline__ uint32_t f2tf32(float f) {
    uint32_t u;
    asm("cvt.rna.tf32.f32 %0, %1;" : "=r"(u) : "f"(f));
    return u;
}

// --- prep: pack weight into per-chunk fragment-paired, pre-swizzled layout ---
// f2 index: s(8) | ks(4) | n(256) | j(4);  stored a = j ^ (n & 2)
// value = { tf32(W[s*32+ks*8+a][n]), tf32(W[s*32+ks*8+a+4][n]) }
__global__ void pack_w_kernel(const float* __restrict__ w) {
    int idx = blockIdx.x * 256 + threadIdx.x;     // 0 .. 65535
    int j  = idx & 3;
    int n  = (idx >> 2) & 255;
    int ks = (idx >> 10) & 3;
    int s  = idx >> 12;
    int a  = j ^ (n & 2);
    int k1 = s * 32 + ks * 8 + a;
    float2 v;
    v.x = __uint_as_float(f2tf32(w[k1 * NOUT + n]));
    v.y = __uint_as_float(f2tf32(w[(k1 + 4) * NOUT + n]));
    g_wp[idx] = v;
}

static __device__ __forceinline__ void mma_tf32(float* c, uint32_t a0, uint32_t a1,
                                                uint32_t a2, uint32_t a3,
                                                uint32_t b0, uint32_t b1) {
    asm volatile(
        "mma.sync.aligned.m16n8k8.row.col.f32.tf32.tf32.f32 "
        "{%0,%1,%2,%3}, {%4,%5,%6,%7}, {%8,%9}, {%0,%1,%2,%3};"
        : "+f"(c[0]), "+f"(c[1]), "+f"(c[2]), "+f"(c[3])
        : "r"(a0), "r"(a1), "r"(a2), "r"(a3), "r"(b0), "r"(b1));
}

static __device__ __forceinline__ void cp_async16cg(uint32_t dst, const void* src) {
    asm volatile("cp.async.cg.shared.global [%0], [%1], 16;"
                 :: "r"(dst), "l"(src) : "memory");
}

static __device__ __forceinline__ void lds64(uint32_t& lo, uint32_t& hi, uint32_t addr) {
    asm volatile("ld.shared.v2.b32 {%0,%1}, [%2];" : "=r"(lo), "=r"(hi) : "r"(addr));
}

static __device__ __forceinline__ void sts64(uint32_t addr, uint32_t lo, uint32_t hi) {
    asm volatile("st.shared.v2.b32 [%0], {%1,%2};" :: "r"(addr), "r"(lo), "r"(hi) : "memory");
}

// ============================================================================
__global__ __launch_bounds__(256, 2) void shiftconv_mma(
    const float* __restrict__ x,
    const float* __restrict__ bias,
    const int* __restrict__ shift_h,
    const int* __restrict__ shift_w,
    float* __restrict__ out)
{
    extern __shared__ float smem[];
    // [A0 | A1 | B0 | B1 | sh 256 | sw 256 | bias 256]
    float* A_s0   = smem;
    float* B_s0   = smem + 4 * A_F2;
    int*   sh_s   = (int*)(smem + 4 * A_F2 + 4 * B_F2);
    int*   sw_s   = sh_s + 256;
    float* bias_s = (float*)(sw_s + 256);

    int tid  = threadIdx.x;
    int lane = tid & 31;
    int warp_n = tid >> 5;      // 8 N-warps (32 cols each); all warps span M 0..63

    sh_s[tid]   = shift_h[tid];
    sw_s[tid]   = shift_w[tid];
    bias_s[tid] = bias[tid];

    int m0   = blockIdx.x * 64;
    int nimg = m0 >> 12;
    int pix0 = m0 & 4095;
    int yrow = pix0 >> 6;        // all 64 pixels share one image row
    const float* xb = x + (size_t)nimg * (CIN * HW);

    // gather ownership: pixel mloc (= x coord), channel-octet kg
    int mloc = tid & 63;
    int kg   = tid >> 6;         // 0..3 == ks
    int aswz = (mloc >> 2) & 3;

    uint32_t a_smem[2], b_smem[2];
    a_smem[0] = (uint32_t)__cvta_generic_to_shared(A_s0);
    a_smem[1] = a_smem[0] + A_F2 * 8;
    b_smem[0] = (uint32_t)__cvta_generic_to_shared(B_s0);
    b_smem[1] = b_smem[0] + B_F2 * 8;

    __syncthreads();

    // ---- staging helpers ----
    #define CP_B(s_, buf) do {                                                 \
        const float2* src = g_wp + (size_t)(s_) * B_F2;                        \
        _Pragma("unroll")                                                      \
        for (int it = 0; it < 8; ++it) {                                       \
            int g = it * 256 + tid;          /* 16B granule = 2 f2 */          \
            cp_async16cg(b_smem[buf] + (uint32_t)g * 16, src + g * 2);         \
        }                                                                      \
        asm volatile("cp.async.commit_group;" ::: "memory");                   \
    } while (0)

    // row-bounds check is per-channel scalar (uniform): y fixed per CTA
    #define GATHER_A(c0, regs) do {                                            \
        _Pragma("unroll")                                                      \
        for (int i = 0; i < 8; ++i) {                                          \
            int c  = (c0) + kg * 8 + i;                                        \
            int sy = yrow + sh_s[c];                                           \
            int sx = mloc + sw_s[c];                                           \
            float v = 0.f;                                                     \
            if ((unsigned)sy < 64u && (unsigned)sx < 64u)                      \
                v = __ldg(xb + (size_t)c * HW + sy * 64 + sx);                 \
            regs[i] = v;                                                       \
        }                                                                      \
    } while (0)

    // STS.64 pairs {k, k+4}: f2 index = (kg*64 + mloc)*4 + (i ^ aswz)
    #define STS_A(regs, buf) do {                                              \
        uint32_t base = a_smem[buf] + (uint32_t)((kg * 64 + mloc) * 4) * 8;    \
        _Pragma("unroll")                                                      \
        for (int i = 0; i < 4; ++i)                                            \
            sts64(base + (uint32_t)(i ^ aswz) * 8,                             \
                  f2tf32(regs[i]), f2tf32(regs[i + 4]));                       \
    } while (0)

    float acc[4][4][4];
    #pragma unroll
    for (int mt = 0; mt < 4; ++mt)
        #pragma unroll
        for (int nt = 0; nt < 4; ++nt)
            #pragma unroll
            for (int e = 0; e < 4; ++e) acc[mt][nt][e] = 0.f;

    // ---- prologue: stage chunk 0 ----
    {
        CP_B(0, 0);
        float regs[8];
        GATHER_A(0, regs);
        STS_A(regs, 0);
        asm volatile("cp.async.wait_group 0;" ::: "memory");
        __syncthreads();
    }

    // fragment indices
    int fa   = lane & 3;                      // a_k
    int fmof = lane >> 2;
    int fn0  = warp_n * 32 + fmof;

    // ---- mainloop: 8 K-chunks of 32 ----
    for (int s = 0; s < 8; ++s) {
        int b = s & 1;
        float pregs[8];
        if (s < 7) {
            CP_B(s + 1, b ^ 1);
            GATHER_A((s + 1) * 32, pregs);    // LDGs overlap compute below
        }

        #pragma unroll
        for (int ks = 0; ks < 4; ++ks) {
            uint32_t afr[4][4], bfr[4][2];
            #pragma unroll
            for (int mt = 0; mt < 4; ++mt) {
                int m = fmof + mt * 16;
                int sz = fa ^ ((m >> 2) & 3);
                uint32_t ab = a_smem[b] + (uint32_t)((ks * 64 + m) * 4 + sz) * 8;
                lds64(afr[mt][0], afr[mt][2], ab);                    // {k,k+4} @ m
                int m8 = m + 8;
                int sz8 = fa ^ ((m8 >> 2) & 3);
                uint32_t ab8 = a_smem[b] + (uint32_t)((ks * 64 + m8) * 4 + sz8) * 8;
                lds64(afr[mt][1], afr[mt][3], ab8);                   // {k,k+4} @ m+8
            }
            #pragma unroll
            for (int nt = 0; nt < 4; ++nt) {
                int n = fn0 + nt * 8;
                uint32_t bb = b_smem[b] + (uint32_t)((ks * 256 + n) * 4 + (fa ^ (n & 2))) * 8;
                lds64(bfr[nt][0], bfr[nt][1], bb);                    // {k,k+4} @ n
            }
            #pragma unroll
            for (int mt = 0; mt < 4; ++mt)
                #pragma unroll
                for (int nt = 0; nt < 4; ++nt)
                    mma_tf32(acc[mt][nt], afr[mt][0], afr[mt][1], afr[mt][2],
                             afr[mt][3], bfr[nt][0], bfr[nt][1]);
        }

        if (s < 7) STS_A(pregs, b ^ 1);
        asm volatile("cp.async.wait_group 0;" ::: "memory");
        __syncthreads();
    }

    // ---- epilogue: bias + store out[n][d][pixel] ----
    float* ob = out + (size_t)nimg * (NOUT * HW) + pix0;
    #pragma unroll
    for (int mt = 0; mt < 4; ++mt) {
        int m_ = mt * 16 + (lane >> 2);
        #pragma unroll
        for (int nt = 0; nt < 4; ++nt) {
            int d_ = warp_n * 32 + nt * 8 + 2 * (lane & 3);
            float b0 = bias_s[d_], b1 = bias_s[d_ + 1];
            size_t o = (size_t)d_ * HW + m_;
            ob[o]          = acc[mt][nt][0] + b0;
            ob[o + HW]     = acc[mt][nt][1] + b1;
            ob[o + 8]      = acc[mt][nt][2] + b0;
            ob[o + HW + 8] = acc[mt][nt][3] + b1;
        }
    }

    #undef CP_B
    #undef GATHER_A
    #undef STS_A
}

// ============================================================================
extern "C" void kernel_launch(void* const* d_in, const int* in_sizes, int n_in,
                              void* d_out, int out_size) {
    const float* x      = (const float*)d_in[0];
    const float* weight = (const float*)d_in[1];
    const float* bias   = (const float*)d_in[2];
    const int*   sh     = (const int*)d_in[3];
    const int*   sw     = (const int*)d_in[4];
    float*       out    = (float*)d_out;

    // A: 2*8KB, B: 2*32KB, tables: 3KB -> 83968 B per CTA (2 CTAs/SM)
    const int smem_bytes = (4 * A_F2 + 4 * B_F2) * 8 + 3 * 256 * 4;
    static int smem_set = 0;
    if (!smem_set) {
        cudaFuncSetAttribute(shiftconv_mma,
                             cudaFuncAttributeMaxDynamicSharedMemorySize, smem_bytes);
        smem_set = 1;
    }

    pack_w_kernel<<<256, 256>>>(weight);
    // 131072 pixels / 64 per CTA = 2048 CTAs
    shiftconv_mma<<<2048, 256, smem_bytes>>>(x, bias, sh, sw, out);
}

// round 5
// speedup vs baseline: 1.1393x; 1.1393x over previous
#include <cuda_runtime.h>
#include <cstdint>

// ============================================================================
// ShiftConv as gather-GEMM, tf32 mma.sync (sm_80+ PTX, runs on plain sm_103):
//   out[n,d,y,x] = sum_c x[n,c,y+sh[c],x+sw[c]] * W[c,d] + bias[d]
// M = 131072 pixels, K = 256, N = 256.
// CTA tile 64(M) x 256(N), 256 threads (8 warps, warp tile 64x32).
// K chunked 16 x 16 (small smem: 43 KB/CTA -> guaranteed 2 CTAs/SM).
// Double-buffered, float2-packed mma fragments in smem.
// ============================================================================

#define CIN   256
#define NOUT  256
#define HW    4096

// A stage: float2[2 ks][64 m][4 a]   (4 KB), slot swizzle a ^= (m>>2)&3
#define A_F2   512
// B stage: float2[2 ks][256 n][4 a] (16 KB), slot swizzle a ^= n&2 (baked in gmem)
#define B_F2   2048
#define NCH    16            // K chunks of 16

__device__ float2 g_wp[CIN * NOUT / 2];   // packed tf32 weight (256 KB)

static __device__ __forceinline__ uint32_t f2tf32(float f) {
    uint32_t u;
    asm("cvt.rna.tf32.f32 %0, %1;" : "=r"(u) : "f"(f));
    return u;
}

// --- prep: pack weight, fragment-paired + pre-swizzled ---
// f2 index: s(16) | ks(2) | n(256) | j(4); stored a = j ^ (n & 2)
// value = { tf32(W[s*16+ks*8+a][n]), tf32(W[s*16+ks*8+a+4][n]) }
__global__ void pack_w_kernel(const float* __restrict__ w) {
    int idx = blockIdx.x * 256 + threadIdx.x;     // 0 .. 32767
    int j  = idx & 3;
    int n  = (idx >> 2) & 255;
    int ks = (idx >> 10) & 1;
    int s  = idx >> 11;
    int a  = j ^ (n & 2);
    int k1 = s * 16 + ks * 8 + a;
    float2 v;
    v.x = __uint_as_float(f2tf32(w[k1 * NOUT + n]));
    v.y = __uint_as_float(f2tf32(w[(k1 + 4) * NOUT + n]));
    g_wp[idx] = v;
}

static __device__ __forceinline__ void mma_tf32(float* c, uint32_t a0, uint32_t a1,
                                                uint32_t a2, uint32_t a3,
                                                uint32_t b0, uint32_t b1) {
    asm volatile(
        "mma.sync.aligned.m16n8k8.row.col.f32.tf32.tf32.f32 "
        "{%0,%1,%2,%3}, {%4,%5,%6,%7}, {%8,%9}, {%0,%1,%2,%3};"
        : "+f"(c[0]), "+f"(c[1]), "+f"(c[2]), "+f"(c[3])
        : "r"(a0), "r"(a1), "r"(a2), "r"(a3), "r"(b0), "r"(b1));
}

static __device__ __forceinline__ void cp_async16cg(uint32_t dst, const void* src) {
    asm volatile("cp.async.cg.shared.global [%0], [%1], 16;"
                 :: "r"(dst), "l"(src) : "memory");
}

static __device__ __forceinline__ void lds64(uint32_t& lo, uint32_t& hi, uint32_t addr) {
    asm volatile("ld.shared.v2.b32 {%0,%1}, [%2];" : "=r"(lo), "=r"(hi) : "r"(addr));
}

static __device__ __forceinline__ void sts64(uint32_t addr, uint32_t lo, uint32_t hi) {
    asm volatile("st.shared.v2.b32 [%0], {%1,%2};" :: "r"(addr), "r"(lo), "r"(hi) : "memory");
}

// ============================================================================
__global__ __launch_bounds__(256, 2) void shiftconv_mma(
    const float* __restrict__ x,
    const float* __restrict__ bias,
    const int* __restrict__ shift_h,
    const int* __restrict__ shift_w,
    float* __restrict__ out)
{
    extern __shared__ float smem[];
    // [A0 | A1 | B0 | B1 | sh 256 | sw 256 | bias 256]
    float* A_s0   = smem;
    float* B_s0   = smem + 4 * A_F2;
    int*   sh_s   = (int*)(smem + 4 * A_F2 + 4 * B_F2);
    int*   sw_s   = sh_s + 256;
    float* bias_s = (float*)(sw_s + 256);

    int tid  = threadIdx.x;
    int lane = tid & 31;
    int warp_n = tid >> 5;       // 8 N-warps (32 cols each)

    sh_s[tid]   = shift_h[tid];
    sw_s[tid]   = shift_w[tid];
    bias_s[tid] = bias[tid];

    int m0   = blockIdx.x * 64;
    int nimg = m0 >> 12;
    int pix0 = m0 & 4095;
    int yrow = pix0 >> 6;        // one image row per CTA
    const float* xb = x + (size_t)nimg * (CIN * HW);

    // gather ownership: pixel mloc, (ks, a-pair) = kq
    int mloc = tid & 63;
    int kq   = tid >> 6;         // 0..3
    int gks  = kq >> 1;          // ks of this thread's channels
    int gah  = (kq & 1) * 2;     // a base (2 a-slots per thread)
    int aswz = (mloc >> 2) & 3;

    uint32_t a_smem[2], b_smem[2];
    a_smem[0] = (uint32_t)__cvta_generic_to_shared(A_s0);
    a_smem[1] = a_smem[0] + A_F2 * 8;
    b_smem[0] = (uint32_t)__cvta_generic_to_shared(B_s0);
    b_smem[1] = b_smem[0] + B_F2 * 8;

    __syncthreads();

    // ---- staging helpers ----
    #define CP_B(s_, buf) do {                                                 \
        const float2* src = g_wp + (size_t)(s_) * B_F2;                        \
        _Pragma("unroll")                                                      \
        for (int it = 0; it < 4; ++it) {                                       \
            int g = it * 256 + tid;              /* 16B = 2 f2 */              \
            cp_async16cg(b_smem[buf] + (uint32_t)g * 16, src + g * 2);         \
        }                                                                      \
        asm volatile("cp.async.commit_group;" ::: "memory");                   \
    } while (0)

    // 4 channels per thread: c = c0 + gks*8 + (gah+i) and +4
    #define GATHER_A(c0, regs) do {                                            \
        _Pragma("unroll")                                                      \
        for (int i = 0; i < 2; ++i) {                                          \
            int c  = (c0) + gks * 8 + gah + i;                                 \
            int sy = yrow + sh_s[c];                                           \
            int sx = mloc + sw_s[c];                                           \
            float v = 0.f;                                                     \
            if ((unsigned)sy < 64u && (unsigned)sx < 64u)                      \
                v = __ldg(xb + (size_t)c * HW + sy * 64 + sx);                 \
            regs[i * 2] = v;                                                   \
            int c4  = c + 4;                                                   \
            int sy4 = yrow + sh_s[c4];                                         \
            int sx4 = mloc + sw_s[c4];                                         \
            float v4 = 0.f;                                                    \
            if ((unsigned)sy4 < 64u && (unsigned)sx4 < 64u)                    \
                v4 = __ldg(xb + (size_t)c4 * HW + sy4 * 64 + sx4);             \
            regs[i * 2 + 1] = v4;                                              \
        }                                                                      \
    } while (0)

    // STS.64 pairs {k, k+4}: f2 index = (gks*64 + mloc)*4 + ((gah+i) ^ aswz)
    #define STS_A(regs, buf) do {                                              \
        uint32_t base = a_smem[buf] + (uint32_t)((gks * 64 + mloc) * 4) * 8;   \
        _Pragma("unroll")                                                      \
        for (int i = 0; i < 2; ++i)                                            \
            sts64(base + (uint32_t)((gah + i) ^ aswz) * 8,                     \
                  f2tf32(regs[i * 2]), f2tf32(regs[i * 2 + 1]));               \
    } while (0)

    float acc[4][4][4];
    #pragma unroll
    for (int mt = 0; mt < 4; ++mt)
        #pragma unroll
        for (int nt = 0; nt < 4; ++nt)
            #pragma unroll
            for (int e = 0; e < 4; ++e) acc[mt][nt][e] = 0.f;

    // ---- prologue: stage chunk 0 ----
    {
        CP_B(0, 0);
        float regs[4];
        GATHER_A(0, regs);
        STS_A(regs, 0);
        asm volatile("cp.async.wait_group 0;" ::: "memory");
        __syncthreads();
    }

    // fragment indices
    int fa   = lane & 3;
    int fmof = lane >> 2;
    int fn0  = warp_n * 32 + fmof;

    // ---- mainloop: 16 K-chunks of 16 ----
    for (int s = 0; s < NCH; ++s) {
        int b = s & 1;
        float pregs[4];
        if (s < NCH - 1) {
            CP_B(s + 1, b ^ 1);
            GATHER_A((s + 1) * 16, pregs);    // LDGs overlap compute below
        }

        #pragma unroll
        for (int ks = 0; ks < 2; ++ks) {
            uint32_t afr[4][4], bfr[4][2];
            #pragma unroll
            for (int mt = 0; mt < 4; ++mt) {
                int m = fmof + mt * 16;
                int sz = fa ^ ((m >> 2) & 3);
                uint32_t ab = a_smem[b] + (uint32_t)((ks * 64 + m) * 4 + sz) * 8;
                lds64(afr[mt][0], afr[mt][2], ab);                    // {k,k+4} @ m
                int m8 = m + 8;
                int sz8 = fa ^ ((m8 >> 2) & 3);
                uint32_t ab8 = a_smem[b] + (uint32_t)((ks * 64 + m8) * 4 + sz8) * 8;
                lds64(afr[mt][1], afr[mt][3], ab8);                   // {k,k+4} @ m+8
            }
            #pragma unroll
            for (int nt = 0; nt < 4; ++nt) {
                int n = fn0 + nt * 8;
                uint32_t bb = b_smem[b] + (uint32_t)((ks * 256 + n) * 4 + (fa ^ (n & 2))) * 8;
                lds64(bfr[nt][0], bfr[nt][1], bb);                    // {k,k+4} @ n
            }
            #pragma unroll
            for (int mt = 0; mt < 4; ++mt)
                #pragma unroll
                for (int nt = 0; nt < 4; ++nt)
                    mma_tf32(acc[mt][nt], afr[mt][0], afr[mt][1], afr[mt][2],
                             afr[mt][3], bfr[nt][0], bfr[nt][1]);
        }

        if (s < NCH - 1) STS_A(pregs, b ^ 1);
        asm volatile("cp.async.wait_group 0;" ::: "memory");
        __syncthreads();
    }

    // ---- epilogue: bias + store out[n][d][pixel] ----
    float* ob = out + (size_t)nimg * (NOUT * HW) + pix0;
    #pragma unroll
    for (int mt = 0; mt < 4; ++mt) {
        int m_ = mt * 16 + (lane >> 2);
        #pragma unroll
        for (int nt = 0; nt < 4; ++nt) {
            int d_ = warp_n * 32 + nt * 8 + 2 * (lane & 3);
            float b0 = bias_s[d_], b1 = bias_s[d_ + 1];
            size_t o = (size_t)d_ * HW + m_;
            ob[o]          = acc[mt][nt][0] + b0;
            ob[o + HW]     = acc[mt][nt][1] + b1;
            ob[o + 8]      = acc[mt][nt][2] + b0;
            ob[o + HW + 8] = acc[mt][nt][3] + b1;
        }
    }

    #undef CP_B
    #undef GATHER_A
    #undef STS_A
}

// ============================================================================
extern "C" void kernel_launch(void* const* d_in, const int* in_sizes, int n_in,
                              void* d_out, int out_size) {
    const float* x      = (const float*)d_in[0];
    const float* weight = (const float*)d_in[1];
    const float* bias   = (const float*)d_in[2];
    const int*   sh     = (const int*)d_in[3];
    const int*   sw     = (const int*)d_in[4];
    float*       out    = (float*)d_out;

    // A: 2*4KB, B: 2*16KB, tables: 3KB -> ~43.3 KB per CTA (2 CTAs/SM by smem)
    const int smem_bytes = (4 * A_F2 + 4 * B_F2) * 8 + 3 * 256 * 4;
    static int attr_set = 0;
    if (!attr_set) {
        cudaFuncSetAttribute(shiftconv_mma,
                             cudaFuncAttributeMaxDynamicSharedMemorySize, smem_bytes);
        cudaFuncSetAttribute(shiftconv_mma,
                             cudaFuncAttributePreferredSharedMemoryCarveout, 100);
        attr_set = 1;
    }

    pack_w_kernel<<<128, 256>>>(weight);
    // 131072 pixels / 64 per CTA = 2048 CTAs
    shiftconv_mma<<<2048, 256, smem_bytes>>>(x, bias, sh, sw, out);
}

// round 6
// speedup vs baseline: 1.3691x; 1.2016x over previous
#include <cuda_runtime.h>
#include <cstdint>

// ============================================================================
// ShiftConv as gather-GEMM, tf32 mma.sync (sm_80+ PTX, runs on plain sm_103):
//   out[n,d,y,x] = sum_c x[n,c,y+sh[c],x+sw[c]] * W[c,d] + bias[d]
// M = 131072 pixels, K = 256, N = 256.
// CTA 128(M) x 256(N), 512 thr (16 warps, warp tile 64x32), K chunk 32 x 8,
// double-buffered. float4-packed fragments: 1 LDS.128 = full mma A operand.
// ============================================================================

#define CIN   256
#define NOUT  256
#define HW    4096

// A stage: f4[4 ks][8 g][8 r][4 a'] = 1024 f4 = 16 KB / buffer
#define A_F4   1024
// B stage: f4[2 kss][256 n][4 a']  = 2048 f4 = 32 KB / buffer
#define B_F4   2048
#define NCH    8

__device__ float4 g_wp[CIN * NOUT / 4];   // packed tf32 weight, 256 KB

static __device__ __forceinline__ uint32_t f2tf32(float f) {
    uint32_t u;
    asm("cvt.rna.tf32.f32 %0, %1;" : "=r"(u) : "f"(f));
    return u;
}

// --- prep: pack W into f4 {W[k0][n],W[k0+4][n],W[k0+8][n],W[k0+12][n]} ---
// f4 index: s(8)|kss(2)|n(256)|a'(4); a = a' ^ ((n>>1)&3); k0 = s*32+kss*16+a
__global__ void pack_w_kernel(const float* __restrict__ w) {
    int t = blockIdx.x * 256 + threadIdx.x;     // 0..16383
    int ap  = t & 3;
    int n   = (t >> 2) & 255;
    int kss = (t >> 10) & 1;
    int s   = t >> 11;
    int a   = ap ^ ((n >> 1) & 3);
    int k0  = s * 32 + kss * 16 + a;
    float4 v;
    v.x = __uint_as_float(f2tf32(w[(k0     ) * NOUT + n]));
    v.y = __uint_as_float(f2tf32(w[(k0 +  4) * NOUT + n]));
    v.z = __uint_as_float(f2tf32(w[(k0 +  8) * NOUT + n]));
    v.w = __uint_as_float(f2tf32(w[(k0 + 12) * NOUT + n]));
    g_wp[t] = v;
}

static __device__ __forceinline__ void mma_tf32(float* c, uint32_t a0, uint32_t a1,
                                                uint32_t a2, uint32_t a3,
                                                uint32_t b0, uint32_t b1) {
    asm volatile(
        "mma.sync.aligned.m16n8k8.row.col.f32.tf32.tf32.f32 "
        "{%0,%1,%2,%3}, {%4,%5,%6,%7}, {%8,%9}, {%0,%1,%2,%3};"
        : "+f"(c[0]), "+f"(c[1]), "+f"(c[2]), "+f"(c[3])
        : "r"(a0), "r"(a1), "r"(a2), "r"(a3), "r"(b0), "r"(b1));
}

static __device__ __forceinline__ void cp_async16cg(uint32_t dst, const void* src) {
    asm volatile("cp.async.cg.shared.global [%0], [%1], 16;"
                 :: "r"(dst), "l"(src) : "memory");
}

static __device__ __forceinline__ void lds128(uint32_t& r0, uint32_t& r1,
                                              uint32_t& r2, uint32_t& r3, uint32_t a) {
    asm volatile("ld.shared.v4.b32 {%0,%1,%2,%3}, [%4];"
                 : "=r"(r0), "=r"(r1), "=r"(r2), "=r"(r3) : "r"(a));
}

static __device__ __forceinline__ void sts64(uint32_t addr, uint32_t lo, uint32_t hi) {
    asm volatile("st.shared.v2.b32 [%0], {%1,%2};" :: "r"(addr), "r"(lo), "r"(hi) : "memory");
}

// ============================================================================
__global__ __launch_bounds__(512, 1) void shiftconv_mma(
    const float* __restrict__ x,
    const float* __restrict__ bias,
    const int* __restrict__ shift_h,
    const int* __restrict__ shift_w,
    float* __restrict__ out)
{
    extern __shared__ float smem[];
    // [A0 f4 | A1 f4 | B0 f4 | B1 f4 | shw 256 | bias 256]
    float* A0_p   = smem;
    float* B0_p   = smem + 8 * A_F4;
    int*   shw_s  = (int*)(smem + 8 * A_F4 + 8 * B_F4);
    float* bias_s = (float*)(shw_s + 256);

    int tid  = threadIdx.x;
    int lane = tid & 31;
    int wid  = tid >> 5;
    int warp_m = wid & 1;         // 2 M-warps (64 rows)
    int warp_n = wid >> 1;        // 4 N-warps (... 8 warps? no: wid>>1 in 0..7)

    // NOTE: 16 warps: warp_m = wid & 1, warp_n = wid >> 1 (0..7), 8 x 32 = 256 N
    if (tid < 256) {
        shw_s[tid]  = (shift_h[tid] << 16) | (shift_w[tid] & 0xffff);
        bias_s[tid] = bias[tid];
    }

    int m0   = blockIdx.x * 128;
    int nimg = m0 >> 12;
    int pix0 = m0 & 4095;
    const float* xb = x + (size_t)nimg * (CIN * HW);

    // gather ownership: pixel mloc (0..127), channel octet kg (0..3)
    int mloc = tid & 127;
    int kg   = tid >> 7;
    int y    = (pix0 + mloc) >> 6;
    int xc   = mloc & 63;

    // A staging address pieces
    int sg    = mloc >> 4;            // g
    int sr    = mloc & 7;             // r
    int shalf = (mloc >> 3) & 1;
    int sswz  = (sr >> 1) & 3;

    uint32_t a_smem[2], b_smem[2];
    a_smem[0] = (uint32_t)__cvta_generic_to_shared(A0_p);
    a_smem[1] = a_smem[0] + A_F4 * 16;
    b_smem[0] = (uint32_t)__cvta_generic_to_shared(B0_p);
    b_smem[1] = b_smem[0] + B_F4 * 16;

    // staging STS base (without a-slot term)
    uint32_t sts_base = (uint32_t)(((kg * 8 + sg) * 8 + sr) * 64 + shalf * 8);

    __syncthreads();

    #define CP_B(s_, buf) do {                                                 \
        const float4* src = g_wp + (size_t)(s_) * B_F4;                        \
        _Pragma("unroll")                                                      \
        for (int it = 0; it < 4; ++it) {                                       \
            int g = it * 512 + tid;                                            \
            cp_async16cg(b_smem[buf] + (uint32_t)g * 16, src + g);             \
        }                                                                      \
        asm volatile("cp.async.commit_group;" ::: "memory");                   \
    } while (0)

    #define GATHER_A(c0, regs) do {                                            \
        _Pragma("unroll")                                                      \
        for (int i = 0; i < 8; ++i) {                                          \
            int c  = (c0) + kg * 8 + i;                                        \
            int w_ = shw_s[c];                                                 \
            int sy = y + (w_ >> 16);                                           \
            int sx = xc + ((w_ << 16) >> 16);                                  \
            float v = 0.f;                                                     \
            if ((unsigned)sy < 64u && (unsigned)sx < 64u)                      \
                v = __ldg(xb + (size_t)c * HW + sy * 64 + sx);                 \
            regs[i] = v;                                                       \
        }                                                                      \
    } while (0)

    // STS.64 halves of f4 slots: pairs {k=kg*8+a, k+4} at this pixel
    #define STS_A(regs, buf) do {                                              \
        uint32_t base = a_smem[buf] + sts_base;                                \
        _Pragma("unroll")                                                      \
        for (int a = 0; a < 4; ++a)                                            \
            sts64(base + (uint32_t)((a ^ sswz) * 16),                          \
                  f2tf32(regs[a]), f2tf32(regs[a + 4]));                       \
    } while (0)

    float acc[4][4][4];
    #pragma unroll
    for (int mt = 0; mt < 4; ++mt)
        #pragma unroll
        for (int nt = 0; nt < 4; ++nt)
            #pragma unroll
            for (int e = 0; e < 4; ++e) acc[mt][nt][e] = 0.f;

    // ---- prologue ----
    {
        CP_B(0, 0);
        float regs[8];
        GATHER_A(0, regs);
        STS_A(regs, 0);
        asm volatile("cp.async.wait_group 0;" ::: "memory");
        __syncthreads();
    }

    // ---- per-thread fragment load bases (swizzles are thread-constant) ----
    int fa = lane & 3;
    int fr = lane >> 2;               // r for A, n-offset for B
    // A: byte = (ks*8 + g)*512 + fr*64 + (fa ^ ((fr>>1)&3))*16 ; g = warp_m*4+mt
    uint32_t a_tbase = (uint32_t)(fr * 64 + (fa ^ ((fr >> 1) & 3)) * 16
                                  + warp_m * 4 * 512);
    // B: byte = kss*16384 + (warp_n*32 + nt*8)*64 + fr*64 + (fa ^ ((fr>>1)&3))*16
    uint32_t b_tbase = (uint32_t)(warp_n * 32 * 64 + fr * 64
                                  + (fa ^ ((fr >> 1) & 3)) * 16);

    // ---- mainloop: 8 chunks of K=32 ----
    for (int s = 0; s < NCH; ++s) {
        int b = s & 1;
        float pregs[8];
        if (s < NCH - 1) {
            CP_B(s + 1, b ^ 1);
            GATHER_A((s + 1) * 32, pregs);   // LDGs overlap compute
        }

        #pragma unroll
        for (int kss = 0; kss < 2; ++kss) {
            // B fragments for both ks of this kss (4 f4 = 16 regs)
            uint32_t bf[4][4];
            #pragma unroll
            for (int nt = 0; nt < 4; ++nt)
                lds128(bf[nt][0], bf[nt][1], bf[nt][2], bf[nt][3],
                       b_smem[b] + b_tbase + (uint32_t)(kss * 16384 + nt * 512));

            #pragma unroll
            for (int ksh = 0; ksh < 2; ++ksh) {
                int ks = kss * 2 + ksh;
                uint32_t af[4][4];
                #pragma unroll
                for (int mt = 0; mt < 4; ++mt)
                    lds128(af[mt][0], af[mt][1], af[mt][2], af[mt][3],
                           a_smem[b] + a_tbase + (uint32_t)((ks * 8 + mt) * 512));
                #pragma unroll
                for (int mt = 0; mt < 4; ++mt)
                    #pragma unroll
                    for (int nt = 0; nt < 4; ++nt)
                        mma_tf32(acc[mt][nt],
                                 af[mt][0], af[mt][2], af[mt][1], af[mt][3],
                                 bf[nt][2 * ksh], bf[nt][2 * ksh + 1]);
            }
        }

        if (s < NCH - 1) STS_A(pregs, b ^ 1);
        asm volatile("cp.async.wait_group 0;" ::: "memory");
        __syncthreads();
    }

    // ---- epilogue: bias + store out[n][d][pixel] ----
    float* ob = out + (size_t)nimg * (NOUT * HW) + pix0;
    #pragma unroll
    for (int mt = 0; mt < 4; ++mt) {
        int m_ = warp_m * 64 + mt * 16 + (lane >> 2);
        #pragma unroll
        for (int nt = 0; nt < 4; ++nt) {
            int d_ = warp_n * 32 + nt * 8 + 2 * (lane & 3);
            float b0 = bias_s[d_], b1 = bias_s[d_ + 1];
            size_t o = (size_t)d_ * HW + m_;
            ob[o]          = acc[mt][nt][0] + b0;
            ob[o + HW]     = acc[mt][nt][1] + b1;
            ob[o + 8]      = acc[mt][nt][2] + b0;
            ob[o + HW + 8] = acc[mt][nt][3] + b1;
        }
    }

    #undef CP_B
    #undef GATHER_A
    #undef STS_A
}

// ============================================================================
extern "C" void kernel_launch(void* const* d_in, const int* in_sizes, int n_in,
                              void* d_out, int out_size) {
    const float* x      = (const float*)d_in[0];
    const float* weight = (const float*)d_in[1];
    const float* bias   = (const float*)d_in[2];
    const int*   sh     = (const int*)d_in[3];
    const int*   sw     = (const int*)d_in[4];
    float*       out    = (float*)d_out;

    // A 2x16KB + B 2x32KB + tables 2KB = 100352 B
    const int smem_bytes = (2 * A_F4 + 2 * B_F4) * 16 + 2 * 256 * 4;
    static int attr_set = 0;
    if (!attr_set) {
        cudaFuncSetAttribute(shiftconv_mma,
                             cudaFuncAttributeMaxDynamicSharedMemorySize, smem_bytes);
        attr_set = 1;
    }

    pack_w_kernel<<<64, 256>>>(weight);
    // 131072 pixels / 128 per CTA = 1024 CTAs
    shiftconv_mma<<<1024, 512, smem_bytes>>>(x, bias, sh, sw, out);
}

// round 7
// speedup vs baseline: 2.1348x; 1.5593x over previous
#include <cuda_runtime.h>
#include <cstdint>

// ============================================================================
// ShiftConv as gather-GEMM, fp16 mma.sync m16n8k16 (fp32 accum):
//   out[n,d,y,x] = sum_c x[n,c,y+sh[c],x+sw[c]] * W[c,d] + bias[d]
// M = 131072 pixels, K = 256, N = 256.
// fp16 has the same 11-bit significand as tf32 (same accuracy, ~3e-4) but
// 2x FLOP/instr and half the operand bytes.
// CTA 128(M) x 256(N), 512 thr (16 warps, warp tile 64x32), K chunk 32 x 8,
// double-buffered; 1 LDS.128 = full mma A operand / full B (both k-steps).
// ============================================================================

#define CIN   256
#define NOUT  256
#define HW    4096

// A stage: f4[2 ks][8 g][8 r][4 a'] = 512 f4 = 8 KB / buffer
#define A_F4   512
// B stage: f4[256 n][4 a'] = 1024 f4 = 16 KB / buffer (both k-steps packed)
#define B_F4   1024
#define NCH    8

__device__ float4 g_wp[NCH * B_F4];   // packed fp16 weight, 128 KB

static __device__ __forceinline__ uint32_t f16x2(float hi, float lo) {
    uint32_t d;
    asm("cvt.rn.f16x2.f32 %0, %1, %2;" : "=r"(d) : "f"(hi), "f"(lo));
    return d;
}

// --- prep: pack W into fp16 f4 slots, fragment-paired + pre-swizzled ---
// f4 index: s(8)|n(256)|a'(4); a = a' ^ ((n>>1)&3); c0 = s*32 + a*2
// words: w0={W[c0],W[c0+1]}, w1={+8,+9}, w2={+16,+17}, w3={+24,+25} (all @ n)
__global__ void pack_w_kernel(const float* __restrict__ w) {
    int t = blockIdx.x * 256 + threadIdx.x;     // 0..8191
    int ap = t & 3;
    int n  = (t >> 2) & 255;
    int s  = t >> 10;
    int a  = ap ^ ((n >> 1) & 3);
    int c0 = s * 32 + a * 2;
    float4 v;
    v.x = __uint_as_float(f16x2(w[(c0 +  1) * NOUT + n], w[(c0     ) * NOUT + n]));
    v.y = __uint_as_float(f16x2(w[(c0 +  9) * NOUT + n], w[(c0 +  8) * NOUT + n]));
    v.z = __uint_as_float(f16x2(w[(c0 + 17) * NOUT + n], w[(c0 + 16) * NOUT + n]));
    v.w = __uint_as_float(f16x2(w[(c0 + 25) * NOUT + n], w[(c0 + 24) * NOUT + n]));
    g_wp[t] = v;
}

static __device__ __forceinline__ void mma_f16(float* c, uint32_t a0, uint32_t a1,
                                               uint32_t a2, uint32_t a3,
                                               uint32_t b0, uint32_t b1) {
    asm volatile(
        "mma.sync.aligned.m16n8k16.row.col.f32.f16.f16.f32 "
        "{%0,%1,%2,%3}, {%4,%5,%6,%7}, {%8,%9}, {%0,%1,%2,%3};"
        : "+f"(c[0]), "+f"(c[1]), "+f"(c[2]), "+f"(c[3])
        : "r"(a0), "r"(a1), "r"(a2), "r"(a3), "r"(b0), "r"(b1));
}

static __device__ __forceinline__ void cp_async16cg(uint32_t dst, const void* src) {
    asm volatile("cp.async.cg.shared.global [%0], [%1], 16;"
                 :: "r"(dst), "l"(src) : "memory");
}

static __device__ __forceinline__ void lds128(uint32_t& r0, uint32_t& r1,
                                              uint32_t& r2, uint32_t& r3, uint32_t a) {
    asm volatile("ld.shared.v4.b32 {%0,%1,%2,%3}, [%4];"
                 : "=r"(r0), "=r"(r1), "=r"(r2), "=r"(r3) : "r"(a));
}

static __device__ __forceinline__ void sts32(uint32_t addr, uint32_t v) {
    asm volatile("st.shared.b32 [%0], %1;" :: "r"(addr), "r"(v) : "memory");
}

// ============================================================================
__global__ __launch_bounds__(512, 1) void shiftconv_mma(
    const float* __restrict__ x,
    const float* __restrict__ bias,
    const int* __restrict__ shift_h,
    const int* __restrict__ shift_w,
    float* __restrict__ out)
{
    extern __shared__ float smem[];
    // [A0 f4 | A1 f4 | B0 f4 | B1 f4 | shw 256 | bias 256]
    float* A0_p   = smem;
    float* B0_p   = smem + 8 * A_F4;
    int*   shw_s  = (int*)(smem + 8 * A_F4 + 8 * B_F4);
    float* bias_s = (float*)(shw_s + 256);

    int tid  = threadIdx.x;
    int lane = tid & 31;
    int wid  = tid >> 5;
    int warp_m = wid & 1;        // 2 M-warps (64 rows each)
    int warp_n = wid >> 1;       // 8 N-warps (32 cols each)

    if (tid < 256) {
        shw_s[tid]  = (shift_h[tid] << 16) | (shift_w[tid] & 0xffff);
        bias_s[tid] = bias[tid];
    }

    int m0   = blockIdx.x * 128;
    int nimg = m0 >> 12;
    int pix0 = m0 & 4095;
    const float* xb = x + (size_t)nimg * (CIN * HW);

    // gather ownership: pixel mloc (0..127), channel octet kg (0..3)
    int mloc = tid & 127;
    int kg   = tid >> 7;
    int y    = (pix0 + mloc) >> 6;
    int xc   = mloc & 63;

    // A staging address: ks=kg>>1, h=kg&1, g=mloc>>4, r=mloc&7, mhalf=(mloc>>3)&1
    int sks   = kg >> 1;
    int sw_w  = (kg & 1) * 2 + ((mloc >> 3) & 1);   // word index in f4
    int sg    = mloc >> 4;
    int sr    = mloc & 7;
    int sswz  = (sr >> 1) & 3;

    uint32_t a_smem[2], b_smem[2];
    a_smem[0] = (uint32_t)__cvta_generic_to_shared(A0_p);
    a_smem[1] = a_smem[0] + A_F4 * 16;
    b_smem[0] = (uint32_t)__cvta_generic_to_shared(B0_p);
    b_smem[1] = b_smem[0] + B_F4 * 16;

    uint32_t sts_base = (uint32_t)(sks * 4096 + sg * 512 + sr * 64 + sw_w * 4);

    __syncthreads();

    #define CP_B(s_, buf) do {                                                 \
        const float4* src = g_wp + (size_t)(s_) * B_F4;                        \
        _Pragma("unroll")                                                      \
        for (int it = 0; it < 2; ++it) {                                       \
            int g = it * 512 + tid;                                            \
            cp_async16cg(b_smem[buf] + (uint32_t)g * 16, src + g);             \
        }                                                                      \
        asm volatile("cp.async.commit_group;" ::: "memory");                   \
    } while (0)

    #define GATHER_A(c0, regs) do {                                            \
        _Pragma("unroll")                                                      \
        for (int i = 0; i < 8; ++i) {                                          \
            int c  = (c0) + kg * 8 + i;                                        \
            int w_ = shw_s[c];                                                 \
            int sy = y + (w_ >> 16);                                           \
            int sx = xc + ((w_ << 16) >> 16);                                  \
            float v = 0.f;                                                     \
            if ((unsigned)sy < 64u && (unsigned)sx < 64u)                      \
                v = __ldg(xb + (size_t)c * HW + sy * 64 + sx);                 \
            regs[i] = v;                                                       \
        }                                                                      \
    } while (0)

    // 4 STS.32: word sw_w of f4 slot (sks, sg, sr, a^sswz), a = 0..3
    #define STS_A(regs, buf) do {                                              \
        uint32_t base = a_smem[buf] + sts_base;                                \
        _Pragma("unroll")                                                      \
        for (int a = 0; a < 4; ++a)                                            \
            sts32(base + (uint32_t)((a ^ sswz) * 16),                          \
                  f16x2(regs[2 * a + 1], regs[2 * a]));                        \
    } while (0)

    float acc[4][4][4];
    #pragma unroll
    for (int mt = 0; mt < 4; ++mt)
        #pragma unroll
        for (int nt = 0; nt < 4; ++nt)
            #pragma unroll
            for (int e = 0; e < 4; ++e) acc[mt][nt][e] = 0.f;

    // ---- prologue ----
    {
        CP_B(0, 0);
        float regs[8];
        GATHER_A(0, regs);
        STS_A(regs, 0);
        asm volatile("cp.async.wait_group 0;" ::: "memory");
        __syncthreads();
    }

    // ---- per-thread fragment bases (swizzles thread-constant) ----
    int fa = lane & 3;
    int fr = lane >> 2;
    uint32_t fswz = (uint32_t)((fa ^ ((fr >> 1) & 3)) * 16);
    // A: ks*4096 + (warp_m*4+mt)*512 + fr*64 + fswz
    uint32_t a_tbase = (uint32_t)(warp_m * 4 * 512 + fr * 64) + fswz;
    // B: (warp_n*32 + nt*8 + fr)*64 + fswz
    uint32_t b_tbase = (uint32_t)((warp_n * 32 + fr) * 64) + fswz;

    // ---- mainloop: 8 chunks of K=32 ----
    for (int s = 0; s < NCH; ++s) {
        int b = s & 1;
        float pregs[8];
        if (s < NCH - 1) {
            CP_B(s + 1, b ^ 1);
            GATHER_A((s + 1) * 32, pregs);   // LDGs overlap compute
        }

        // B fragments: one LDS.128 per nt covers BOTH k-steps
        uint32_t bf[4][4];
        #pragma unroll
        for (int nt = 0; nt < 4; ++nt)
            lds128(bf[nt][0], bf[nt][1], bf[nt][2], bf[nt][3],
                   b_smem[b] + b_tbase + (uint32_t)(nt * 512));

        #pragma unroll
        for (int ks = 0; ks < 2; ++ks) {
            uint32_t af[4][4];
            #pragma unroll
            for (int mt = 0; mt < 4; ++mt)
                lds128(af[mt][0], af[mt][1], af[mt][2], af[mt][3],
                       a_smem[b] + a_tbase + (uint32_t)(ks * 4096 + mt * 512));
            #pragma unroll
            for (int mt = 0; mt < 4; ++mt)
                #pragma unroll
                for (int nt = 0; nt < 4; ++nt)
                    mma_f16(acc[mt][nt],
                            af[mt][0], af[mt][1], af[mt][2], af[mt][3],
                            bf[nt][2 * ks], bf[nt][2 * ks + 1]);
        }

        if (s < NCH - 1) STS_A(pregs, b ^ 1);
        asm volatile("cp.async.wait_group 0;" ::: "memory");
        __syncthreads();
    }

    // ---- epilogue: bias + store out[n][d][pixel] ----
    float* ob = out + (size_t)nimg * (NOUT * HW) + pix0;
    #pragma unroll
    for (int mt = 0; mt < 4; ++mt) {
        int m_ = warp_m * 64 + mt * 16 + (lane >> 2);
        #pragma unroll
        for (int nt = 0; nt < 4; ++nt) {
            int d_ = warp_n * 32 + nt * 8 + 2 * (lane & 3);
            float b0 = bias_s[d_], b1 = bias_s[d_ + 1];
            size_t o = (size_t)d_ * HW + m_;
            ob[o]          = acc[mt][nt][0] + b0;
            ob[o + HW]     = acc[mt][nt][1] + b1;
            ob[o + 8]      = acc[mt][nt][2] + b0;
            ob[o + HW + 8] = acc[mt][nt][3] + b1;
        }
    }

    #undef CP_B
    #undef GATHER_A
    #undef STS_A
}

// ============================================================================
extern "C" void kernel_launch(void* const* d_in, const int* in_sizes, int n_in,
                              void* d_out, int out_size) {
    const float* x      = (const float*)d_in[0];
    const float* weight = (const float*)d_in[1];
    const float* bias   = (const float*)d_in[2];
    const int*   sh     = (const int*)d_in[3];
    const int*   sw     = (const int*)d_in[4];
    float*       out    = (float*)d_out;

    // A 2x8KB + B 2x16KB + tables 2KB = 51200 B
    const int smem_bytes = (2 * A_F4 + 2 * B_F4) * 16 + 2 * 256 * 4;
    static int attr_set = 0;
    if (!attr_set) {
        cudaFuncSetAttribute(shiftconv_mma,
                             cudaFuncAttributeMaxDynamicSharedMemorySize, smem_bytes);
        attr_set = 1;
    }

    pack_w_kernel<<<32, 256>>>(weight);
    // 131072 pixels / 128 per CTA = 1024 CTAs
    shiftconv_mma<<<1024, 512, smem_bytes>>>(x, bias, sh, sw, out);
}